// round 1
// baseline (speedup 1.0000x reference)
#include <cuda_runtime.h>

#define Bdim 8
#define Wdim 4096
#define Rdim 128
#define Ddim 128
#define BLK  128
#define NBLK 32

// Scratch (allocation-free rule: __device__ globals)
__device__ float g_ptab[129 * 128];                    // ptab[i*128+r] = gamma_r^i, i=0..128
__device__ float g_ntab[128 * 128];                    // ntab[j*128+r] = gamma_r^{-j}
__device__ float g_A[Bdim * NBLK * BLK * BLK];         // masked decay-weighted attention per block
__device__ float g_U[Bdim * NBLK * Rdim * Ddim];       // per-block state increment
__device__ float g_S[Bdim * NBLK * Rdim * Ddim];       // prefix state BEFORE block n

// ---------------------------------------------------------------------------
// Power table: gamma^i and gamma^-j
// ---------------------------------------------------------------------------
__global__ void pow_kernel(const float* __restrict__ gamma) {
    int r = threadIdx.x;          // 0..127
    int row = blockIdx.x;         // 0..256
    float lg = logf(gamma[r]);
    if (row < 129) {
        g_ptab[row * 128 + r] = expf((float)row * lg);
    } else {
        int j = row - 129;        // 0..127
        g_ntab[j * 128 + r] = expf(-(float)j * lg);
    }
}

// ---------------------------------------------------------------------------
// Phase 1a: A[i,j] = mask(i>=j) * sum_r (q[i,r]*g^i) (k[j,r]*g^-j)
// One CTA per (n,b). 256 threads, 8x8 register tile, K-chunk 16.
// ---------------------------------------------------------------------------
__global__ __launch_bounds__(256) void matA_kernel(const float* __restrict__ q,
                                                   const float* __restrict__ k) {
    int n = blockIdx.x, b = blockIdx.y;
    int tid = threadIdx.x;
    int tx = tid & 15, ty = tid >> 4;

    __shared__ float Qs[16][132];   // [k][i], padded
    __shared__ float Ks[16][132];   // [k][j]

    const int base_in = (b * Wdim + n * BLK) * Rdim;

    float acc[8][8];
#pragma unroll
    for (int ii = 0; ii < 8; ii++)
#pragma unroll
        for (int jj = 0; jj < 8; jj++) acc[ii][jj] = 0.f;

    for (int kc = 0; kc < Rdim; kc += 16) {
#pragma unroll
        for (int t = 0; t < 2; t++) {
            int f4  = tid + t * 256;          // 0..511
            int row = f4 >> 2;                // 0..127
            int c4  = (f4 & 3) * 4;           // 0,4,8,12
            int col = kc + c4;
            float4 qv = *(const float4*)(q + base_in + row * Rdim + col);
            float4 pv = *(const float4*)(g_ptab + row * 128 + col);
            Qs[c4 + 0][row] = qv.x * pv.x;
            Qs[c4 + 1][row] = qv.y * pv.y;
            Qs[c4 + 2][row] = qv.z * pv.z;
            Qs[c4 + 3][row] = qv.w * pv.w;
            float4 kv = *(const float4*)(k + base_in + row * Rdim + col);
            float4 nv = *(const float4*)(g_ntab + row * 128 + col);
            Ks[c4 + 0][row] = kv.x * nv.x;
            Ks[c4 + 1][row] = kv.y * nv.y;
            Ks[c4 + 2][row] = kv.z * nv.z;
            Ks[c4 + 3][row] = kv.w * nv.w;
        }
        __syncthreads();
#pragma unroll
        for (int kk = 0; kk < 16; kk++) {
            float4 a0 = *(const float4*)&Qs[kk][ty * 8];
            float4 a1 = *(const float4*)&Qs[kk][ty * 8 + 4];
            float4 b0 = *(const float4*)&Ks[kk][tx * 8];
            float4 b1 = *(const float4*)&Ks[kk][tx * 8 + 4];
            float a[8] = {a0.x, a0.y, a0.z, a0.w, a1.x, a1.y, a1.z, a1.w};
            float bb[8] = {b0.x, b0.y, b0.z, b0.w, b1.x, b1.y, b1.z, b1.w};
#pragma unroll
            for (int ii = 0; ii < 8; ii++)
#pragma unroll
                for (int jj = 0; jj < 8; jj++)
                    acc[ii][jj] = fmaf(a[ii], bb[jj], acc[ii][jj]);
        }
        __syncthreads();
    }

    float* outA = g_A + (b * NBLK + n) * (BLK * BLK);
#pragma unroll
    for (int ii = 0; ii < 8; ii++) {
        int i = ty * 8 + ii;
#pragma unroll
        for (int jj = 0; jj < 8; jj++) {
            int j = tx * 8 + jj;
            if (i < j) acc[ii][jj] = 0.f;
        }
        *(float4*)(outA + i * BLK + tx * 8) =
            make_float4(acc[ii][0], acc[ii][1], acc[ii][2], acc[ii][3]);
        *(float4*)(outA + i * BLK + tx * 8 + 4) =
            make_float4(acc[ii][4], acc[ii][5], acc[ii][6], acc[ii][7]);
    }
}

// ---------------------------------------------------------------------------
// Phase 1b: U[r,d] = sum_j (k[j,r]*g^(127-j)) * h[j,d]
// Both operands are K(=j)-major in gmem: direct smem loads, no transpose.
// ---------------------------------------------------------------------------
__global__ __launch_bounds__(256) void matU_kernel(const float* __restrict__ k,
                                                   const float* __restrict__ h) {
    int n = blockIdx.x, b = blockIdx.y;
    int tid = threadIdx.x;
    int tx = tid & 15, ty = tid >> 4;

    __shared__ float Ks[16][128];   // [j][r]
    __shared__ float Hs[16][128];   // [j][d]

    const int kbase = (b * Wdim + n * BLK) * Rdim;
    const int hbase = (b * Wdim + n * BLK) * Ddim;

    float acc[8][8];
#pragma unroll
    for (int ii = 0; ii < 8; ii++)
#pragma unroll
        for (int jj = 0; jj < 8; jj++) acc[ii][jj] = 0.f;

    for (int jc = 0; jc < BLK; jc += 16) {
#pragma unroll
        for (int t = 0; t < 2; t++) {
            int f4   = tid + t * 256;
            int jrow = f4 >> 5;               // 0..15
            int c    = (f4 & 31) * 4;         // 0..124
            int j    = jc + jrow;
            float4 kv = *(const float4*)(k + kbase + j * Rdim + c);
            float4 pv = *(const float4*)(g_ptab + (127 - j) * 128 + c);
            *(float4*)&Ks[jrow][c] =
                make_float4(kv.x * pv.x, kv.y * pv.y, kv.z * pv.z, kv.w * pv.w);
            *(float4*)&Hs[jrow][c] = *(const float4*)(h + hbase + j * Ddim + c);
        }
        __syncthreads();
#pragma unroll
        for (int kk = 0; kk < 16; kk++) {
            float4 a0 = *(const float4*)&Ks[kk][ty * 8];
            float4 a1 = *(const float4*)&Ks[kk][ty * 8 + 4];
            float4 b0 = *(const float4*)&Hs[kk][tx * 8];
            float4 b1 = *(const float4*)&Hs[kk][tx * 8 + 4];
            float a[8] = {a0.x, a0.y, a0.z, a0.w, a1.x, a1.y, a1.z, a1.w};
            float bb[8] = {b0.x, b0.y, b0.z, b0.w, b1.x, b1.y, b1.z, b1.w};
#pragma unroll
            for (int ii = 0; ii < 8; ii++)
#pragma unroll
                for (int jj = 0; jj < 8; jj++)
                    acc[ii][jj] = fmaf(a[ii], bb[jj], acc[ii][jj]);
        }
        __syncthreads();
    }

    float* outU = g_U + (b * NBLK + n) * (Rdim * Ddim);
#pragma unroll
    for (int ii = 0; ii < 8; ii++) {
        int r = ty * 8 + ii;
        *(float4*)(outU + r * Ddim + tx * 8) =
            make_float4(acc[ii][0], acc[ii][1], acc[ii][2], acc[ii][3]);
        *(float4*)(outU + r * Ddim + tx * 8 + 4) =
            make_float4(acc[ii][4], acc[ii][5], acc[ii][6], acc[ii][7]);
    }
}

// ---------------------------------------------------------------------------
// Phase 2: prefix-state scan. S_prev[n] = g^128 * S_prev[n-1] + U[n-1], S_prev[0]=0
// ---------------------------------------------------------------------------
__global__ void scan_kernel() {
    int gid = blockIdx.x * 256 + threadIdx.x;   // 0..131071
    int b  = gid >> 14;                         // /16384
    int rd = gid & 16383;
    int r  = rd >> 7;
    float gdec = g_ptab[128 * 128 + r];         // gamma_r^128
    float s = 0.f;
    int base = b * NBLK * 16384 + rd;
#pragma unroll 1
    for (int n = 0; n < NBLK; n++) {
        int off = base + n * 16384;
        g_S[off] = s;
        s = fmaf(s, gdec, 0.f) + g_U[off];      // s*gdec + U
    }
}

// ---------------------------------------------------------------------------
// Phase 3: out[i,d] = sum_j A[i,j] h[j,d] + sum_r (q[i,r]*g^(i+1)) S_prev[r,d]
// ---------------------------------------------------------------------------
__global__ __launch_bounds__(256) void out_kernel(const float* __restrict__ q,
                                                  const float* __restrict__ h,
                                                  float* __restrict__ out) {
    int n = blockIdx.x, b = blockIdx.y;
    int tid = threadIdx.x;
    int tx = tid & 15, ty = tid >> 4;

    __shared__ float As[16][132];   // [k][i], padded (transposed operand)
    __shared__ float Bs[16][128];   // [k][d]

    const float* Ablk = g_A + (b * NBLK + n) * (BLK * BLK);
    const float* Sblk = g_S + (b * NBLK + n) * (Rdim * Ddim);
    const int hbase = (b * Wdim + n * BLK) * Ddim;
    const int qbase = (b * Wdim + n * BLK) * Rdim;

    float acc[8][8];
#pragma unroll
    for (int ii = 0; ii < 8; ii++)
#pragma unroll
        for (int jj = 0; jj < 8; jj++) acc[ii][jj] = 0.f;

    // ---- part 1: A @ H (reduce over j) ----
    for (int kc = 0; kc < BLK; kc += 16) {
#pragma unroll
        for (int t = 0; t < 2; t++) {
            int f4  = tid + t * 256;
            int row = f4 >> 2;
            int c4  = (f4 & 3) * 4;
            int col = kc + c4;
            float4 av = *(const float4*)(Ablk + row * BLK + col);
            As[c4 + 0][row] = av.x;
            As[c4 + 1][row] = av.y;
            As[c4 + 2][row] = av.z;
            As[c4 + 3][row] = av.w;
            int jrow = f4 >> 5;
            int c    = (f4 & 31) * 4;
            *(float4*)&Bs[jrow][c] =
                *(const float4*)(h + hbase + (kc + jrow) * Ddim + c);
        }
        __syncthreads();
#pragma unroll
        for (int kk = 0; kk < 16; kk++) {
            float4 a0 = *(const float4*)&As[kk][ty * 8];
            float4 a1 = *(const float4*)&As[kk][ty * 8 + 4];
            float4 b0 = *(const float4*)&Bs[kk][tx * 8];
            float4 b1 = *(const float4*)&Bs[kk][tx * 8 + 4];
            float a[8] = {a0.x, a0.y, a0.z, a0.w, a1.x, a1.y, a1.z, a1.w};
            float bb[8] = {b0.x, b0.y, b0.z, b0.w, b1.x, b1.y, b1.z, b1.w};
#pragma unroll
            for (int ii = 0; ii < 8; ii++)
#pragma unroll
                for (int jj = 0; jj < 8; jj++)
                    acc[ii][jj] = fmaf(a[ii], bb[jj], acc[ii][jj]);
        }
        __syncthreads();
    }

    // ---- part 2: (Q * g^(i+1)) @ S_prev (reduce over r) ----
    for (int kc = 0; kc < Rdim; kc += 16) {
#pragma unroll
        for (int t = 0; t < 2; t++) {
            int f4  = tid + t * 256;
            int row = f4 >> 2;
            int c4  = (f4 & 3) * 4;
            int col = kc + c4;
            float4 qv = *(const float4*)(q + qbase + row * Rdim + col);
            float4 pv = *(const float4*)(g_ptab + (row + 1) * 128 + col);
            As[c4 + 0][row] = qv.x * pv.x;
            As[c4 + 1][row] = qv.y * pv.y;
            As[c4 + 2][row] = qv.z * pv.z;
            As[c4 + 3][row] = qv.w * pv.w;
            int rrow = f4 >> 5;
            int c    = (f4 & 31) * 4;
            *(float4*)&Bs[rrow][c] =
                *(const float4*)(Sblk + (kc + rrow) * Ddim + c);
        }
        __syncthreads();
#pragma unroll
        for (int kk = 0; kk < 16; kk++) {
            float4 a0 = *(const float4*)&As[kk][ty * 8];
            float4 a1 = *(const float4*)&As[kk][ty * 8 + 4];
            float4 b0 = *(const float4*)&Bs[kk][tx * 8];
            float4 b1 = *(const float4*)&Bs[kk][tx * 8 + 4];
            float a[8] = {a0.x, a0.y, a0.z, a0.w, a1.x, a1.y, a1.z, a1.w};
            float bb[8] = {b0.x, b0.y, b0.z, b0.w, b1.x, b1.y, b1.z, b1.w};
#pragma unroll
            for (int ii = 0; ii < 8; ii++)
#pragma unroll
                for (int jj = 0; jj < 8; jj++)
                    acc[ii][jj] = fmaf(a[ii], bb[jj], acc[ii][jj]);
        }
        __syncthreads();
    }

    float* o = out + (b * Wdim + n * BLK) * Ddim;
#pragma unroll
    for (int ii = 0; ii < 8; ii++) {
        int i = ty * 8 + ii;
        *(float4*)(o + i * Ddim + tx * 8) =
            make_float4(acc[ii][0], acc[ii][1], acc[ii][2], acc[ii][3]);
        *(float4*)(o + i * Ddim + tx * 8 + 4) =
            make_float4(acc[ii][4], acc[ii][5], acc[ii][6], acc[ii][7]);
    }
}

// ---------------------------------------------------------------------------
extern "C" void kernel_launch(void* const* d_in, const int* in_sizes, int n_in,
                              void* d_out, int out_size) {
    const float* q     = (const float*)d_in[0];   // [B, W, R]
    const float* k     = (const float*)d_in[1];   // [B, W, R]
    const float* h     = (const float*)d_in[2];   // [B, W, D]
    const float* gamma = (const float*)d_in[3];   // [R]
    float* out = (float*)d_out;                   // [B, W, D]

    pow_kernel<<<257, 128>>>(gamma);
    dim3 grid(NBLK, Bdim);
    matA_kernel<<<grid, 256>>>(q, k);
    matU_kernel<<<grid, 256>>>(k, h);
    scan_kernel<<<512, 256>>>();
    out_kernel<<<grid, 256>>>(q, h, out);
}

// round 4
// speedup vs baseline: 1.0139x; 1.0139x over previous
#include <cuda_runtime.h>

#define Bdim 8
#define Wdim 4096
#define Rdim 128
#define Ddim 128
#define BLK  128
#define NBLK 32

// Scratch (allocation-free rule: __device__ globals)
__device__ float g_ptab[129 * 128];                    // ptab[i*128+r] = gamma_r^i, i=0..128
__device__ float g_ntab[128 * 128];                    // ntab[j*128+r] = gamma_r^{-j}
__device__ float g_A[Bdim * NBLK * BLK * BLK];
__device__ float g_U[Bdim * NBLK * Rdim * Ddim];
__device__ float g_S[Bdim * NBLK * Rdim * Ddim];

// ---------------------------------------------------------------------------
// Packed-f32x2 helpers (Blackwell sm_100a: 2 MACs per FFMA2 issue slot)
// ---------------------------------------------------------------------------
__device__ __forceinline__ unsigned long long pack_dup(float a) {
    unsigned long long p;
    unsigned int au = __float_as_uint(a);
    asm("mov.b64 %0, {%1, %1};" : "=l"(p) : "r"(au));
    return p;
}
__device__ __forceinline__ void unpack2(unsigned long long p, float& lo, float& hi) {
    unsigned int l, h;
    asm("mov.b64 {%0, %1}, %2;" : "=r"(l), "=r"(h) : "l"(p));
    lo = __uint_as_float(l);
    hi = __uint_as_float(h);
}
__device__ __forceinline__ void ffma2(unsigned long long& acc,
                                      unsigned long long a, unsigned long long b) {
    asm("fma.rn.f32x2 %0, %1, %2, %0;" : "+l"(acc) : "l"(a), "l"(b));
}

// One k-slice of the 8x8 register tile: 8 a-values (dup-packed) x 4 b-pairs
__device__ __forceinline__ void tile_step(unsigned long long acc[8][4],
                                          const float* __restrict__ Arow,
                                          const float* __restrict__ Brow,
                                          int ty8, int tx8) {
    float4 a0 = *(const float4*)(Arow + ty8);
    float4 a1 = *(const float4*)(Arow + ty8 + 4);
    float av[8] = {a0.x, a0.y, a0.z, a0.w, a1.x, a1.y, a1.z, a1.w};
    const unsigned long long* bp = (const unsigned long long*)(Brow + tx8);
    unsigned long long b[4] = {bp[0], bp[1], bp[2], bp[3]};
#pragma unroll
    for (int ii = 0; ii < 8; ii++) {
        unsigned long long ap = pack_dup(av[ii]);
#pragma unroll
        for (int jj = 0; jj < 4; jj++) ffma2(acc[ii][jj], ap, b[jj]);
    }
}

// ---------------------------------------------------------------------------
// Power table
// ---------------------------------------------------------------------------
__global__ void pow_kernel(const float* __restrict__ gamma) {
    int r = threadIdx.x;
    int row = blockIdx.x;
    float lg = logf(gamma[r]);
    if (row < 129) {
        g_ptab[row * 128 + r] = expf((float)row * lg);
    } else {
        int j = row - 129;
        g_ntab[j * 128 + r] = expf(-(float)j * lg);
    }
}

// ---------------------------------------------------------------------------
// Fused phase 1: z==0 -> A matrix, z==1 -> U matrix. One CTA per (n,b,z).
// ---------------------------------------------------------------------------
__global__ __launch_bounds__(256) void matAU_kernel(const float* __restrict__ q,
                                                    const float* __restrict__ k,
                                                    const float* __restrict__ h) {
    int n = blockIdx.x, b = blockIdx.y;
    int tid = threadIdx.x;
    int tx = tid & 15, ty = tid >> 4;
    int ty8 = ty * 8, tx8 = tx * 8;

    __shared__ __align__(16) float As[16][132];
    __shared__ __align__(16) float Bs[16][132];

    unsigned long long acc[8][4];
#pragma unroll
    for (int ii = 0; ii < 8; ii++)
#pragma unroll
        for (int jj = 0; jj < 4; jj++) acc[ii][jj] = 0ULL;

    if (blockIdx.z == 0) {
        // A[i,j] = mask(i>=j) * sum_r (q[i,r]*g^i)(k[j,r]*g^-j)
        const int base_in = (b * Wdim + n * BLK) * Rdim;
        for (int kc = 0; kc < Rdim; kc += 16) {
#pragma unroll
            for (int t = 0; t < 2; t++) {
                int f4  = tid + t * 256;
                int row = f4 >> 2;
                int c4  = (f4 & 3) * 4;
                int col = kc + c4;
                float4 qv = *(const float4*)(q + base_in + row * Rdim + col);
                float4 pv = *(const float4*)(g_ptab + row * 128 + col);
                As[c4 + 0][row] = qv.x * pv.x;
                As[c4 + 1][row] = qv.y * pv.y;
                As[c4 + 2][row] = qv.z * pv.z;
                As[c4 + 3][row] = qv.w * pv.w;
                float4 kv = *(const float4*)(k + base_in + row * Rdim + col);
                float4 nv = *(const float4*)(g_ntab + row * 128 + col);
                Bs[c4 + 0][row] = kv.x * nv.x;
                Bs[c4 + 1][row] = kv.y * nv.y;
                Bs[c4 + 2][row] = kv.z * nv.z;
                Bs[c4 + 3][row] = kv.w * nv.w;
            }
            __syncthreads();
#pragma unroll
            for (int kk = 0; kk < 16; kk++)
                tile_step(acc, &As[kk][0], &Bs[kk][0], ty8, tx8);
            __syncthreads();
        }
        float* outA = g_A + (b * NBLK + n) * (BLK * BLK);
#pragma unroll
        for (int ii = 0; ii < 8; ii++) {
            int i = ty8 + ii;
            float v[8];
#pragma unroll
            for (int jj = 0; jj < 4; jj++) unpack2(acc[ii][jj], v[2 * jj], v[2 * jj + 1]);
#pragma unroll
            for (int jj = 0; jj < 8; jj++)
                if (i < tx8 + jj) v[jj] = 0.f;
            *(float4*)(outA + i * BLK + tx8)     = make_float4(v[0], v[1], v[2], v[3]);
            *(float4*)(outA + i * BLK + tx8 + 4) = make_float4(v[4], v[5], v[6], v[7]);
        }
    } else {
        // U[r,d] = sum_j (k[j,r]*g^(127-j)) * h[j,d]
        const int kbase = (b * Wdim + n * BLK) * Rdim;
        const int hbase = (b * Wdim + n * BLK) * Ddim;
        for (int jc = 0; jc < BLK; jc += 16) {
#pragma unroll
            for (int t = 0; t < 2; t++) {
                int f4   = tid + t * 256;
                int jrow = f4 >> 5;
                int c    = (f4 & 31) * 4;
                int j    = jc + jrow;
                float4 kv = *(const float4*)(k + kbase + j * Rdim + c);
                float4 pv = *(const float4*)(g_ptab + (127 - j) * 128 + c);
                *(float4*)&As[jrow][c] =
                    make_float4(kv.x * pv.x, kv.y * pv.y, kv.z * pv.z, kv.w * pv.w);
                *(float4*)&Bs[jrow][c] = *(const float4*)(h + hbase + j * Ddim + c);
            }
            __syncthreads();
#pragma unroll
            for (int kk = 0; kk < 16; kk++)
                tile_step(acc, &As[kk][0], &Bs[kk][0], ty8, tx8);
            __syncthreads();
        }
        float* outU = g_U + (b * NBLK + n) * (Rdim * Ddim);
#pragma unroll
        for (int ii = 0; ii < 8; ii++) {
            int r = ty8 + ii;
            float v[8];
#pragma unroll
            for (int jj = 0; jj < 4; jj++) unpack2(acc[ii][jj], v[2 * jj], v[2 * jj + 1]);
            *(float4*)(outU + r * Ddim + tx8)     = make_float4(v[0], v[1], v[2], v[3]);
            *(float4*)(outU + r * Ddim + tx8 + 4) = make_float4(v[4], v[5], v[6], v[7]);
        }
    }
}

// ---------------------------------------------------------------------------
// Phase 2: prefix-state scan with full MLP (preload all 32 U values)
// ---------------------------------------------------------------------------
__global__ void scan_kernel() {
    int gid = blockIdx.x * 256 + threadIdx.x;   // 0..131071
    int b  = gid >> 14;
    int rd = gid & 16383;
    int r  = rd >> 7;
    float gdec = g_ptab[128 * 128 + r];         // gamma_r^128
    int base = b * NBLK * 16384 + rd;
    float u[NBLK];
#pragma unroll
    for (int n = 0; n < NBLK; n++) u[n] = g_U[base + n * 16384];
    float s = 0.f;
#pragma unroll
    for (int n = 0; n < NBLK; n++) {
        g_S[base + n * 16384] = s;
        s = fmaf(s, gdec, u[n]);
    }
}

// ---------------------------------------------------------------------------
// Phase 3: out = A @ H + (Q*g^(i+1)) @ S_prev
// ---------------------------------------------------------------------------
__global__ __launch_bounds__(256) void out_kernel(const float* __restrict__ q,
                                                  const float* __restrict__ h,
                                                  float* __restrict__ out) {
    int n = blockIdx.x, b = blockIdx.y;
    int tid = threadIdx.x;
    int tx = tid & 15, ty = tid >> 4;
    int ty8 = ty * 8, tx8 = tx * 8;

    __shared__ __align__(16) float As[16][132];
    __shared__ __align__(16) float Bs[16][132];

    const float* Ablk = g_A + (b * NBLK + n) * (BLK * BLK);
    const float* Sblk = g_S + (b * NBLK + n) * (Rdim * Ddim);
    const int hbase = (b * Wdim + n * BLK) * Ddim;
    const int qbase = (b * Wdim + n * BLK) * Rdim;

    unsigned long long acc[8][4];
#pragma unroll
    for (int ii = 0; ii < 8; ii++)
#pragma unroll
        for (int jj = 0; jj < 4; jj++) acc[ii][jj] = 0ULL;

    // part 1: A @ H (reduce over j)
    for (int kc = 0; kc < BLK; kc += 16) {
#pragma unroll
        for (int t = 0; t < 2; t++) {
            int f4  = tid + t * 256;
            int row = f4 >> 2;
            int c4  = (f4 & 3) * 4;
            int col = kc + c4;
            float4 av = *(const float4*)(Ablk + row * BLK + col);
            As[c4 + 0][row] = av.x;
            As[c4 + 1][row] = av.y;
            As[c4 + 2][row] = av.z;
            As[c4 + 3][row] = av.w;
            int jrow = f4 >> 5;
            int c    = (f4 & 31) * 4;
            *(float4*)&Bs[jrow][c] =
                *(const float4*)(h + hbase + (kc + jrow) * Ddim + c);
        }
        __syncthreads();
#pragma unroll
        for (int kk = 0; kk < 16; kk++)
            tile_step(acc, &As[kk][0], &Bs[kk][0], ty8, tx8);
        __syncthreads();
    }

    // part 2: (Q * g^(i+1)) @ S_prev (reduce over r)
    for (int kc = 0; kc < Rdim; kc += 16) {
#pragma unroll
        for (int t = 0; t < 2; t++) {
            int f4  = tid + t * 256;
            int row = f4 >> 2;
            int c4  = (f4 & 3) * 4;
            int col = kc + c4;
            float4 qv = *(const float4*)(q + qbase + row * Rdim + col);
            float4 pv = *(const float4*)(g_ptab + (row + 1) * 128 + col);
            As[c4 + 0][row] = qv.x * pv.x;
            As[c4 + 1][row] = qv.y * pv.y;
            As[c4 + 2][row] = qv.z * pv.z;
            As[c4 + 3][row] = qv.w * pv.w;
            int rrow = f4 >> 5;
            int c    = (f4 & 31) * 4;
            *(float4*)&Bs[rrow][c] =
                *(const float4*)(Sblk + (kc + rrow) * Ddim + c);
        }
        __syncthreads();
#pragma unroll
        for (int kk = 0; kk < 16; kk++)
            tile_step(acc, &As[kk][0], &Bs[kk][0], ty8, tx8);
        __syncthreads();
    }

    float* o = out + (b * Wdim + n * BLK) * Ddim;
#pragma unroll
    for (int ii = 0; ii < 8; ii++) {
        int i = ty8 + ii;
        float v[8];
#pragma unroll
        for (int jj = 0; jj < 4; jj++) unpack2(acc[ii][jj], v[2 * jj], v[2 * jj + 1]);
        *(float4*)(o + i * Ddim + tx8)     = make_float4(v[0], v[1], v[2], v[3]);
        *(float4*)(o + i * Ddim + tx8 + 4) = make_float4(v[4], v[5], v[6], v[7]);
    }
}

// ---------------------------------------------------------------------------
extern "C" void kernel_launch(void* const* d_in, const int* in_sizes, int n_in,
                              void* d_out, int out_size) {
    const float* q     = (const float*)d_in[0];
    const float* k     = (const float*)d_in[1];
    const float* h     = (const float*)d_in[2];
    const float* gamma = (const float*)d_in[3];
    float* out = (float*)d_out;

    pow_kernel<<<257, 128>>>(gamma);
    dim3 gridAU(NBLK, Bdim, 2);
    matAU_kernel<<<gridAU, 256>>>(q, k, h);
    scan_kernel<<<512, 256>>>();
    dim3 grid(NBLK, Bdim);
    out_kernel<<<grid, 256>>>(q, h, out);
}

// round 6
// speedup vs baseline: 1.4903x; 1.4699x over previous
#include <cuda_runtime.h>
#include <cuda_bf16.h>
#include <cstdint>

#define Bdim 8
#define Wdim 4096
#define Rdim 128
#define Ddim 128
#define BLK  128
#define NBLK 32

// ---------------------------------------------------------------------------
// Scratch (__device__ globals; allocation-free rule)
// ---------------------------------------------------------------------------
__device__ float g_ptab[129 * 128];   // ptab[i*128+r] = gamma_r^i
__device__ float g_ntab[128 * 128];   // ntab[j*128+r] = gamma_r^{-j}
__device__ float g_A[Bdim * NBLK * BLK * BLK];       // masked A[i][j]
__device__ float g_U[Bdim * NBLK * Ddim * Rdim];     // Ut layout [d][r]
__device__ float g_S[Bdim * NBLK * Ddim * Rdim];     // St layout [d][r]

// ---------------------------------------------------------------------------
// SMEM: 4 bf16 tiles 128 rows x 136 halves (272B/row, conflict-free ldmatrix)
// ---------------------------------------------------------------------------
#define TROWB   272
#define TBYTES  (128 * TROWB)          // 34816
#define SMEM_TOTAL (4 * TBYTES)        // 139264

__device__ __forceinline__ uint32_t smem_u32(const void* p) {
    uint32_t a;
    asm("{ .reg .u64 t; cvta.to.shared.u64 t, %1; cvt.u32.u64 %0, t; }" : "=r"(a) : "l"(p));
    return a;
}

__device__ __forceinline__ void split1(float a, unsigned short& h, unsigned short& l) {
    __nv_bfloat16 hb = __float2bfloat16(a);
    float rem = a - __bfloat162float(hb);
    __nv_bfloat16 lb = __float2bfloat16(rem);
    h = *(unsigned short*)&hb;
    l = *(unsigned short*)&lb;
}
__device__ __forceinline__ unsigned long long pack4(unsigned short a, unsigned short b,
                                                    unsigned short c, unsigned short d) {
    return (unsigned long long)a | ((unsigned long long)b << 16)
         | ((unsigned long long)c << 32) | ((unsigned long long)d << 48);
}

// ---------------------------------------------------------------------------
// Staging into padded bf16 tiles (hi & lo)
// nat: dst[m][c] = src[m][c] * (wt ? wt[(m+wrofs)*128+c] : 1)
// ---------------------------------------------------------------------------
__device__ __forceinline__ void stage_nat(const float* __restrict__ src,
                                          const float* __restrict__ wt, int wrofs,
                                          char* hiT, char* loT, int tid) {
#pragma unroll
    for (int it = 0; it < 16; it++) {
        int t = tid + it * 256;
        int row = t >> 5, c4 = (t & 31) << 2;
        float4 v = *(const float4*)(src + row * 128 + c4);
        if (wt) {
            float4 w = *(const float4*)(wt + (row + wrofs) * 128 + c4);
            v.x *= w.x; v.y *= w.y; v.z *= w.z; v.w *= w.w;
        }
        unsigned short h[4], l[4];
        split1(v.x, h[0], l[0]); split1(v.y, h[1], l[1]);
        split1(v.z, h[2], l[2]); split1(v.w, h[3], l[3]);
        int off = row * TROWB + c4 * 2;
        *(unsigned long long*)(hiT + off) = pack4(h[0], h[1], h[2], h[3]);
        *(unsigned long long*)(loT + off) = pack4(l[0], l[1], l[2], l[3]);
    }
}

// tr: dst[c][j] = src[j][c] * (useW ? ptab[(127-j)*128+c] : 1)
__device__ __forceinline__ void stage_tr(const float* __restrict__ src, bool useW,
                                         char* hiT, char* loT, int tid) {
#pragma unroll
    for (int it = 0; it < 4; it++) {
        int t = tid + it * 256;
        int j0 = (t >> 5) << 2, c0 = (t & 31) << 2;
        unsigned short hs[4][4], ls[4][4];    // [src row x][src col u]
#pragma unroll
        for (int x = 0; x < 4; x++) {
            float4 v = *(const float4*)(src + (j0 + x) * 128 + c0);
            if (useW) {
                float4 w = *(const float4*)(g_ptab + (127 - (j0 + x)) * 128 + c0);
                v.x *= w.x; v.y *= w.y; v.z *= w.z; v.w *= w.w;
            }
            split1(v.x, hs[x][0], ls[x][0]); split1(v.y, hs[x][1], ls[x][1]);
            split1(v.z, hs[x][2], ls[x][2]); split1(v.w, hs[x][3], ls[x][3]);
        }
#pragma unroll
        for (int u = 0; u < 4; u++) {
            int off = (c0 + u) * TROWB + j0 * 2;
            *(unsigned long long*)(hiT + off) = pack4(hs[0][u], hs[1][u], hs[2][u], hs[3][u]);
            *(unsigned long long*)(loT + off) = pack4(ls[0][u], ls[1][u], ls[2][u], ls[3][u]);
        }
    }
}

// ---------------------------------------------------------------------------
// mma.sync path (portable sm_80+ tensor cores)
// ---------------------------------------------------------------------------
__device__ __forceinline__ void ldsm_x4(uint32_t addr, uint32_t& r0, uint32_t& r1,
                                        uint32_t& r2, uint32_t& r3) {
    asm volatile("ldmatrix.sync.aligned.m8n8.x4.shared.b16 {%0,%1,%2,%3}, [%4];"
                 : "=r"(r0), "=r"(r1), "=r"(r2), "=r"(r3) : "r"(addr));
}
__device__ __forceinline__ void mma16816(float* c, uint32_t a0, uint32_t a1,
                                         uint32_t a2, uint32_t a3,
                                         uint32_t b0, uint32_t b1) {
    asm volatile("mma.sync.aligned.m16n8k16.row.col.f32.bf16.bf16.f32 "
                 "{%0,%1,%2,%3}, {%4,%5,%6,%7}, {%8,%9}, {%0,%1,%2,%3};"
                 : "+f"(c[0]), "+f"(c[1]), "+f"(c[2]), "+f"(c[3])
                 : "r"(a0), "r"(a1), "r"(a2), "r"(a3), "r"(b0), "r"(b1));
}

// One product: C[128x128] += Atile[128xK=128] * Btile'[128xK=128]^T
// Warp layout: warp_m = wid&3 (32 rows), warp_n = wid>>2 (64 cols)
__device__ __forceinline__ void gemm_prod(uint32_t aT, uint32_t bT,
                                          int m0, int n0, int lane,
                                          float acc[2][8][4]) {
    int r = lane & 7, sub = lane >> 3;
    // A ldmatrix address pattern: groups (m0-7,k0) (m8-15,k0) (m0-7,k8) (m8-15,k8)
    int aRow = (sub & 1) * 8 + r;
    int aK   = (sub >> 1) * 8;
    // B pattern: (n0-7,k0) (n0-7,k8) (n8-15,k0) (n8-15,k8)
    int bRow = (sub >> 1) * 8 + r;
    int bK   = (sub & 1) * 8;
#pragma unroll
    for (int ks = 0; ks < 8; ks++) {
        int k0 = ks * 16;
        uint32_t a[2][4];
#pragma unroll
        for (int am = 0; am < 2; am++) {
            uint32_t addr = aT + (uint32_t)((m0 + am * 16 + aRow) * TROWB + (k0 + aK) * 2);
            ldsm_x4(addr, a[am][0], a[am][1], a[am][2], a[am][3]);
        }
#pragma unroll
        for (int g = 0; g < 4; g++) {
            uint32_t q0, q1, q2, q3;
            uint32_t addr = bT + (uint32_t)((n0 + g * 16 + bRow) * TROWB + (k0 + bK) * 2);
            ldsm_x4(addr, q0, q1, q2, q3);
#pragma unroll
            for (int am = 0; am < 2; am++) {
                mma16816(acc[am][g * 2 + 0], a[am][0], a[am][1], a[am][2], a[am][3], q0, q1);
                mma16816(acc[am][g * 2 + 1], a[am][0], a[am][1], a[am][2], a[am][3], q2, q3);
            }
        }
    }
}

// bf16x3: hi*hi + hi*lo + lo*hi
__device__ __forceinline__ void gemm3(char* smem, int m0, int n0, int lane,
                                      float acc[2][8][4]) {
    uint32_t AHI = smem_u32(smem);
    uint32_t ALO = AHI + TBYTES;
    uint32_t BHI = AHI + 2 * TBYTES;
    uint32_t BLO = AHI + 3 * TBYTES;
    gemm_prod(AHI, BHI, m0, n0, lane, acc);
    gemm_prod(AHI, BLO, m0, n0, lane, acc);
    gemm_prod(ALO, BHI, m0, n0, lane, acc);
}

// Epilogue: write fragments; optional causal mask (zero where i<j)
__device__ __forceinline__ void epilogue(float acc[2][8][4], float* __restrict__ dst,
                                         bool mask, int m0, int n0, int lane) {
    int t4 = lane >> 2, tp2 = (lane & 3) * 2;
#pragma unroll
    for (int am = 0; am < 2; am++) {
#pragma unroll
        for (int g = 0; g < 8; g++) {
            int col = n0 + g * 8 + tp2;
            int row0 = m0 + am * 16 + t4;
            float c0 = acc[am][g][0], c1 = acc[am][g][1];
            float c2 = acc[am][g][2], c3 = acc[am][g][3];
            if (mask) {
                if (row0 < col)         c0 = 0.f;
                if (row0 < col + 1)     c1 = 0.f;
                if (row0 + 8 < col)     c2 = 0.f;
                if (row0 + 8 < col + 1) c3 = 0.f;
            }
            *(float2*)(dst + row0 * 128 + col)       = make_float2(c0, c1);
            *(float2*)(dst + (row0 + 8) * 128 + col) = make_float2(c2, c3);
        }
    }
}

__device__ __forceinline__ void zero_acc(float acc[2][8][4]) {
#pragma unroll
    for (int am = 0; am < 2; am++)
#pragma unroll
        for (int g = 0; g < 8; g++)
#pragma unroll
            for (int e = 0; e < 4; e++) acc[am][g][e] = 0.f;
}

// ---------------------------------------------------------------------------
// Power tables
// ---------------------------------------------------------------------------
__global__ void pow_kernel(const float* __restrict__ gamma) {
    int r = threadIdx.x, row = blockIdx.x;
    float lg = logf(gamma[r]);
    if (row < 129) g_ptab[row * 128 + r] = expf((float)row * lg);
    else           g_ntab[(row - 129) * 128 + r] = expf(-(float)(row - 129) * lg);
}

// ---------------------------------------------------------------------------
// Phase 1 (z=0): A[i,j] = mask * sum_r (q g^i)(k g^-j); (z=1): Ut[d,r]
// ---------------------------------------------------------------------------
__global__ __launch_bounds__(256) void matAU_kernel(const float* __restrict__ q,
                                                    const float* __restrict__ k,
                                                    const float* __restrict__ h) {
    extern __shared__ __align__(16) char smem[];
    int n = blockIdx.x, b = blockIdx.y;
    int tid = threadIdx.x, wid = tid >> 5, lane = tid & 31;
    int m0 = (wid & 3) * 32, n0 = (wid >> 2) * 64;

    const int in_base = (b * Wdim + n * BLK) * Rdim;
    if (blockIdx.z == 0) {
        stage_nat(q + in_base, g_ptab, 0, smem, smem + TBYTES, tid);
        stage_nat(k + in_base, g_ntab, 0, smem + 2 * TBYTES, smem + 3 * TBYTES, tid);
    } else {
        stage_tr(h + in_base, false, smem, smem + TBYTES, tid);               // A[d][j]=h[j][d]
        stage_tr(k + in_base, true,  smem + 2 * TBYTES, smem + 3 * TBYTES, tid); // B'[r][j]=k*g^(127-j)
    }
    __syncthreads();

    float acc[2][8][4];
    zero_acc(acc);
    gemm3(smem, m0, n0, lane, acc);

    float* dst = (blockIdx.z == 0) ? g_A + (b * NBLK + n) * (BLK * BLK)
                                   : g_U + (b * NBLK + n) * (Ddim * Rdim);
    epilogue(acc, dst, blockIdx.z == 0, m0, n0, lane);
}

// ---------------------------------------------------------------------------
// Phase 2: prefix scan on [d][r] state, MLP-32 preload
// ---------------------------------------------------------------------------
__global__ void scan_kernel() {
    int gid = blockIdx.x * 256 + threadIdx.x;   // 131072
    int b = gid >> 14, dr = gid & 16383, r = dr & 127;
    float gdec = g_ptab[128 * 128 + r];         // gamma_r^128
    int base = b * NBLK * 16384 + dr;
    float u[NBLK];
#pragma unroll
    for (int nn = 0; nn < NBLK; nn++) u[nn] = g_U[base + nn * 16384];
    float s = 0.f;
#pragma unroll
    for (int nn = 0; nn < NBLK; nn++) {
        g_S[base + nn * 16384] = s;
        s = fmaf(s, gdec, u[nn]);
    }
}

// ---------------------------------------------------------------------------
// Phase 3: out = A @ H + (Q*g^(i+1)) @ St
// ---------------------------------------------------------------------------
__global__ __launch_bounds__(256) void out_kernel(const float* __restrict__ q,
                                                  const float* __restrict__ h,
                                                  float* __restrict__ out) {
    extern __shared__ __align__(16) char smem[];
    int n = blockIdx.x, b = blockIdx.y;
    int tid = threadIdx.x, wid = tid >> 5, lane = tid & 31;
    int m0 = (wid & 3) * 32, n0 = (wid >> 2) * 64;

    const float* Ablk = g_A + (b * NBLK + n) * (BLK * BLK);
    const float* Sblk = g_S + (b * NBLK + n) * (Ddim * Rdim);
    const int hbase = (b * Wdim + n * BLK) * Ddim;
    const int qbase = (b * Wdim + n * BLK) * Rdim;

    float acc[2][8][4];
    zero_acc(acc);

    // part 1: A @ H   (A nat; B'[d][j] = h^T)
    stage_nat(Ablk, (const float*)0, 0, smem, smem + TBYTES, tid);
    stage_tr(h + hbase, false, smem + 2 * TBYTES, smem + 3 * TBYTES, tid);
    __syncthreads();
    gemm3(smem, m0, n0, lane, acc);
    __syncthreads();

    // part 2: (Q * g^(i+1)) @ St   (A nat weighted; B' = St[d][r] nat)
    stage_nat(q + qbase, g_ptab, 1, smem, smem + TBYTES, tid);
    stage_nat(Sblk, (const float*)0, 0, smem + 2 * TBYTES, smem + 3 * TBYTES, tid);
    __syncthreads();
    gemm3(smem, m0, n0, lane, acc);

    epilogue(acc, out + (b * Wdim + n * BLK) * Ddim, false, m0, n0, lane);
}

// ---------------------------------------------------------------------------
extern "C" void kernel_launch(void* const* d_in, const int* in_sizes, int n_in,
                              void* d_out, int out_size) {
    const float* q     = (const float*)d_in[0];
    const float* k     = (const float*)d_in[1];
    const float* h     = (const float*)d_in[2];
    const float* gamma = (const float*)d_in[3];
    float* out = (float*)d_out;

    cudaFuncSetAttribute(matAU_kernel, cudaFuncAttributeMaxDynamicSharedMemorySize, SMEM_TOTAL);
    cudaFuncSetAttribute(out_kernel,   cudaFuncAttributeMaxDynamicSharedMemorySize, SMEM_TOTAL);

    pow_kernel<<<257, 128>>>(gamma);
    matAU_kernel<<<dim3(NBLK, Bdim, 2), 256, SMEM_TOTAL>>>(q, k, h);
    scan_kernel<<<512, 256>>>();
    out_kernel<<<dim3(NBLK, Bdim), 256, SMEM_TOTAL>>>(q, h, out);
}